// round 11
// baseline (speedup 1.0000x reference)
#include <cuda_runtime.h>
#include <cuda_fp16.h>
#include <cstdint>

#define DEVINL __device__ __forceinline__

static constexpr int B_ROWS = 131072;
static constexpr int DIM    = 256;
static constexpr int C_COLS = 1000;
static constexpr int C_PAD  = 1024;

// CTA: 128 M-rows x 512 N-cols (4 n-tiles of 128), K=256 in 4 chunks of 64
static constexpr int TILE_M   = 128;
static constexpr int TILE_N   = 128;
static constexpr int N_TILES  = 4;            // n-tiles per CTA
static constexpr int K_CHUNK  = 64;
static constexpr int K_CHUNKS = DIM / K_CHUNK;       // 4
static constexpr int N_ITERS  = N_TILES * K_CHUNKS;  // 16 chunk iterations
static constexpr int N_STAGES = 3;

static constexpr int A_BYTES      = TILE_M * DIM * 2;        // 65536 (4 chunk regions x 16K)
static constexpr int B_STAGE      = TILE_N * K_CHUNK * 2;    // 16384
static constexpr int SM_A   = 0;
static constexpr int SM_B   = A_BYTES;                        // 3 stages
static constexpr int SM_RX  = SM_B + N_STAGES * B_STAGE;      // 114688
static constexpr int SMEM_REQ = SM_RX + 512;                  // 115200 -> 2 CTAs/SM (225KB)

// w scratch (x is consumed directly by the GEMM now)
__device__ __half g_wh[(size_t)C_PAD * DIM];
__device__ float  g_sw[C_PAD];

// ---------------- helpers ----------------
DEVINL uint32_t smem_u32(const void* p) {
    uint32_t a;
    asm("{ .reg .u64 t; cvta.to.shared.u64 t, %1; cvt.u32.u64 %0, t; }" : "=r"(a) : "l"(p));
    return a;
}
DEVINL void cp16(uint32_t dst, const void* src) {
    asm volatile("cp.async.cg.shared.global [%0], [%1], 16;" :: "r"(dst), "l"(src));
}
DEVINL void cp_commit() { asm volatile("cp.async.commit_group;" ::: "memory"); }
template <int N> DEVINL void cp_wait() {
    asm volatile("cp.async.wait_group %0;" :: "n"(N) : "memory");
}
DEVINL uint32_t sw128(uint32_t off) { return off ^ ((off >> 3) & 0x70); }
DEVINL void sts128(uint32_t addr, uint32_t r0, uint32_t r1, uint32_t r2, uint32_t r3) {
    asm volatile("st.shared.v4.b32 [%0], {%1,%2,%3,%4};"
                 :: "r"(addr), "r"(r0), "r"(r1), "r"(r2), "r"(r3) : "memory");
}
DEVINL float lds_f32(uint32_t addr) {
    float v;
    asm volatile("ld.shared.f32 %0, [%1];" : "=f"(v) : "r"(addr));
    return v;
}

#define LDSM_X4(r0, r1, r2, r3, addr)                                             \
    asm volatile("ldmatrix.sync.aligned.m8n8.x4.shared.b16 {%0,%1,%2,%3}, [%4];"  \
                 : "=r"(r0), "=r"(r1), "=r"(r2), "=r"(r3) : "r"(addr))

DEVINL void mma16816(float* d, const uint32_t* a, const uint32_t* b) {
    asm volatile(
        "mma.sync.aligned.m16n8k16.row.col.f32.f16.f16.f32 "
        "{%0,%1,%2,%3}, {%4,%5,%6,%7}, {%8,%9}, {%0,%1,%2,%3};"
        : "+f"(d[0]), "+f"(d[1]), "+f"(d[2]), "+f"(d[3])
        : "r"(a[0]), "r"(a[1]), "r"(a[2]), "r"(a[3]), "r"(b[0]), "r"(b[1]));
}

// ---------------- prep (w only): fp32 -> fp16 + inverse row L2 norm -----------
__global__ void prep_w_kernel(const float* __restrict__ w) {
    int row  = (blockIdx.x * blockDim.x + threadIdx.x) >> 5;
    int lane = threadIdx.x & 31;
    if (row >= C_PAD) return;
    uint2* drow = reinterpret_cast<uint2*>(g_wh + (size_t)row * DIM);
    if (row < C_COLS) {
        const float4* p = reinterpret_cast<const float4*>(w + (size_t)row * DIM);
        float4 v0 = p[lane];
        float4 v1 = p[lane + 32];
        float s = v0.x * v0.x + v0.y * v0.y + v0.z * v0.z + v0.w * v0.w
                + v1.x * v1.x + v1.y * v1.y + v1.z * v1.z + v1.w * v1.w;
#pragma unroll
        for (int o = 16; o; o >>= 1) s += __shfl_xor_sync(0xFFFFFFFFu, s, o);
        __half2 h0 = __floats2half2_rn(v0.x, v0.y);
        __half2 h1 = __floats2half2_rn(v0.z, v0.w);
        __half2 h2 = __floats2half2_rn(v1.x, v1.y);
        __half2 h3 = __floats2half2_rn(v1.z, v1.w);
        uint2 u0, u1;
        u0.x = *reinterpret_cast<uint32_t*>(&h0);
        u0.y = *reinterpret_cast<uint32_t*>(&h1);
        u1.x = *reinterpret_cast<uint32_t*>(&h2);
        u1.y = *reinterpret_cast<uint32_t*>(&h3);
        drow[lane]      = u0;
        drow[lane + 32] = u1;
        if (lane == 0) g_sw[row] = rsqrtf(s);
    } else {
        uint2 z = {0u, 0u};
        drow[lane]      = z;
        drow[lane + 32] = z;
        if (lane == 0) g_sw[row] = 0.0f;
    }
}

// ---------------- GEMM ----------------
DEVINL void load_b_chunk(uint32_t sB, int n0, int k0, int tid) {
    const __half* wb = g_wh + (size_t)n0 * DIM + k0;
#pragma unroll
    for (int i = 0; i < 4; i++) {                 // 128 rows x 8 x 16B
        int g = tid + i * 256;
        int row = g >> 3, c = g & 7;
        cp16(sB + sw128((uint32_t)(row * 128 + c * 16)), wb + row * DIM + c * 8);
    }
}

__global__ __launch_bounds__(256, 2)
void gemm_kernel(const float* __restrict__ x, float* __restrict__ out) {
    extern __shared__ char smem[];
    uint32_t s0 = smem_u32(smem);
    uint32_t sA_base = s0 + SM_A;
    uint32_t sB_base = s0 + SM_B;
    uint32_t sRX     = s0 + SM_RX;

    int tid  = threadIdx.x;
    int wid  = tid >> 5;
    int lane = tid & 31;
    int bid  = blockIdx.x;
    int m0      = (bid >> 1) * TILE_M;
    int n0_base = (bid & 1) * (N_TILES * TILE_N);

    // kick off B pipeline first (chunks 0,1)
    load_b_chunk(sB_base + 0 * B_STAGE, n0_base, 0 * K_CHUNK, tid);
    cp_commit();
    load_b_chunk(sB_base + 1 * B_STAGE, n0_base, 1 * K_CHUNK, tid);
    cp_commit();

    // ---- build A in smem: fp32 LDG -> fp16, + row rsqrt norms ----
    // iter i, thread t: idx = t + i*256; row = idx>>5 (warp-uniform), unit = idx&31
    // unit = 8 fp16 = 16B dst = 32B src. 16 iters cover 128 rows x 32 units.
#pragma unroll 1
    for (int i = 0; i < 16; i++) {
        int idx  = tid + i * 256;
        int row  = idx >> 5;
        int unit = idx & 31;
        const float4* src = reinterpret_cast<const float4*>(
            x + (size_t)(m0 + row) * DIM + unit * 8);
        float4 v0 = src[0];
        float4 v1 = src[1];
        float s = v0.x * v0.x + v0.y * v0.y + v0.z * v0.z + v0.w * v0.w
                + v1.x * v1.x + v1.y * v1.y + v1.z * v1.z + v1.w * v1.w;
#pragma unroll
        for (int o = 16; o; o >>= 1) s += __shfl_xor_sync(0xFFFFFFFFu, s, o);
        __half2 h0 = __floats2half2_rn(v0.x, v0.y);
        __half2 h1 = __floats2half2_rn(v0.z, v0.w);
        __half2 h2 = __floats2half2_rn(v1.x, v1.y);
        __half2 h3 = __floats2half2_rn(v1.z, v1.w);
        int chunk = unit >> 3, cu = unit & 7;
        uint32_t dst = sA_base + chunk * 16384 + sw128((uint32_t)(row * 128 + cu * 16));
        sts128(dst, *reinterpret_cast<uint32_t*>(&h0), *reinterpret_cast<uint32_t*>(&h1),
                    *reinterpret_cast<uint32_t*>(&h2), *reinterpret_cast<uint32_t*>(&h3));
        if (lane == 0)
            *reinterpret_cast<float*>(smem + SM_RX + row * 4) = rsqrtf(s);
    }

    int warp_m = wid >> 2;       // 0..1  -> 64 rows
    int warp_n = wid & 3;        // 0..3  -> 32 cols
    int a_row  = warp_m * 64 + (lane & 15);
    int a_kadd = (lane & 16) >> 1;               // 0 or 8
    int b_row  = warp_n * 32 + (lane & 7) + ((lane & 16) >> 1);
    int b_kadd = lane & 8;                       // 0 or 8

    float acc[4][4][4];

#pragma unroll 1
    for (int g = 0; g < N_ITERS; g++) {
        int nt = g >> 2;
        int kc = g & 3;
        if (g < N_ITERS - 1) cp_wait<1>();
        else                 cp_wait<0>();
        __syncthreads();

        // prefetch chunk g+2 into ring slot (g+2)%3 (freed by the sync above)
        if (g + 2 < N_ITERS) {
            int g2 = g + 2;
            load_b_chunk(sB_base + (g2 % N_STAGES) * B_STAGE,
                         n0_base + (g2 >> 2) * TILE_N, (g2 & 3) * K_CHUNK, tid);
            cp_commit();
        }

        if (kc == 0) {
#pragma unroll
            for (int i = 0; i < 4; i++)
#pragma unroll
                for (int j = 0; j < 4; j++)
#pragma unroll
                    for (int k = 0; k < 4; k++) acc[i][j][k] = 0.0f;
        }

        uint32_t sA = sA_base + kc * 16384;
        uint32_t sB = sB_base + (g % N_STAGES) * B_STAGE;
#pragma unroll
        for (int ks = 0; ks < 4; ks++) {
            uint32_t a[4][4];
#pragma unroll
            for (int bm = 0; bm < 4; bm++) {
                int row  = a_row + bm * 16;
                int kcol = ks * 16 + a_kadd;
                LDSM_X4(a[bm][0], a[bm][1], a[bm][2], a[bm][3],
                        sA + sw128((uint32_t)(row * 128 + kcol * 2)));
            }
            uint32_t b[2][4];
#pragma unroll
            for (int bb = 0; bb < 2; bb++) {
                int row  = b_row + bb * 16;
                int kcol = ks * 16 + b_kadd;
                LDSM_X4(b[bb][0], b[bb][1], b[bb][2], b[bb][3],
                        sB + sw128((uint32_t)(row * 128 + kcol * 2)));
            }
#pragma unroll
            for (int bm = 0; bm < 4; bm++)
#pragma unroll
                for (int bb = 0; bb < 2; bb++) {
                    mma16816(acc[bm][2 * bb],     a[bm], &b[bb][0]);
                    mma16816(acc[bm][2 * bb + 1], a[bm], &b[bb][2]);
                }
        }

        // per-n-tile epilogue after its last k-chunk (overlaps with in-flight B loads)
        if (kc == 3) {
            int n0 = n0_base + nt * TILE_N;
#pragma unroll
            for (int bm = 0; bm < 4; bm++) {
                int ml = warp_m * 64 + bm * 16 + (lane >> 2);
                float ra = 2.0f * lds_f32(sRX + ml * 4);
                float rb = 2.0f * lds_f32(sRX + (ml + 8) * 4);
                float* rowa = out + (size_t)(m0 + ml) * C_COLS;
                float* rowb = out + (size_t)(m0 + ml + 8) * C_COLS;
#pragma unroll
                for (int bn = 0; bn < 4; bn++) {
                    int col = n0 + warp_n * 32 + bn * 8 + (lane & 3) * 2;
                    if (col < C_COLS) {
                        float sc0 = g_sw[col];
                        float sc1 = g_sw[col + 1];
                        float2 va, vb;
                        va.x = fminf(fmaf(ra * sc0, acc[bm][bn][0], -2.0f), 0.0f);
                        va.y = fminf(fmaf(ra * sc1, acc[bm][bn][1], -2.0f), 0.0f);
                        vb.x = fminf(fmaf(rb * sc0, acc[bm][bn][2], -2.0f), 0.0f);
                        vb.y = fminf(fmaf(rb * sc1, acc[bm][bn][3], -2.0f), 0.0f);
                        *reinterpret_cast<float2*>(rowa + col) = va;
                        *reinterpret_cast<float2*>(rowb + col) = vb;
                    }
                }
            }
        }
    }
}

// ---------------- launch ----------------
extern "C" void kernel_launch(void* const* d_in, const int* in_sizes, int n_in,
                              void* d_out, int out_size) {
    const float* x = (const float*)d_in[0];
    const float* w = (const float*)d_in[1];
    float* out = (float*)d_out;

    cudaFuncSetAttribute(gemm_kernel, cudaFuncAttributeMaxDynamicSharedMemorySize, SMEM_REQ);

    prep_w_kernel<<<C_PAD / 8, 256>>>(w);

    // 1024 m-tiles x 2 n-halves; each CTA covers 128 x 512
    gemm_kernel<<<(B_ROWS / TILE_M) * 2, 256, SMEM_REQ>>>(x, out);

    // weight passthrough (second output)
    long long logits_elems = (long long)B_ROWS * C_COLS;
    if ((long long)out_size >= logits_elems + (long long)C_COLS * DIM) {
        cudaMemcpyAsync(out + logits_elems, w, (size_t)C_COLS * DIM * sizeof(float),
                        cudaMemcpyDeviceToDevice);
    }
}

// round 12
// speedup vs baseline: 1.1384x; 1.1384x over previous
#include <cuda_runtime.h>
#include <cuda_fp16.h>
#include <cstdint>

#define DEVINL __device__ __forceinline__

static constexpr int B_ROWS = 131072;
static constexpr int DIM    = 256;
static constexpr int C_COLS = 1000;
static constexpr int C_PAD  = 1024;

// CTA: 128 M-rows x 512 N-cols (4 n-tiles of 128), K=256 in 4 chunks of 64
static constexpr int TILE_M   = 128;
static constexpr int TILE_N   = 128;
static constexpr int N_TILES  = 4;
static constexpr int K_CHUNK  = 64;
static constexpr int K_CHUNKS = DIM / K_CHUNK;       // 4
static constexpr int N_ITERS  = N_TILES * K_CHUNKS;  // 16
static constexpr int N_STAGES = 3;

static constexpr int A_BYTES  = TILE_M * DIM * 2;        // 65536 (4 chunk regions x 16K)
static constexpr int B_STAGE  = TILE_N * K_CHUNK * 2;    // 16384
static constexpr int SM_A   = 0;
static constexpr int SM_B   = A_BYTES;
static constexpr int SM_RX  = SM_B + N_STAGES * B_STAGE; // 114688
static constexpr int SMEM_REQ = SM_RX + 512;             // 115200 -> 2 CTAs/SM

// scratch
__device__ __half g_xh[(size_t)B_ROWS * DIM];
__device__ __half g_wh[(size_t)C_PAD * DIM];
__device__ float  g_rx[B_ROWS];
__device__ float  g_sw[C_PAD];

// ---------------- helpers ----------------
DEVINL uint32_t smem_u32(const void* p) {
    uint32_t a;
    asm("{ .reg .u64 t; cvta.to.shared.u64 t, %1; cvt.u32.u64 %0, t; }" : "=r"(a) : "l"(p));
    return a;
}
DEVINL void cp16(uint32_t dst, const void* src) {
    asm volatile("cp.async.cg.shared.global [%0], [%1], 16;" :: "r"(dst), "l"(src));
}
DEVINL void cp_commit() { asm volatile("cp.async.commit_group;" ::: "memory"); }
template <int N> DEVINL void cp_wait() {
    asm volatile("cp.async.wait_group %0;" :: "n"(N) : "memory");
}
DEVINL uint32_t sw128(uint32_t off) { return off ^ ((off >> 3) & 0x70); }
DEVINL float lds_f32(uint32_t addr) {
    float v;
    asm volatile("ld.shared.f32 %0, [%1];" : "=f"(v) : "r"(addr));
    return v;
}

#define LDSM_X4(r0, r1, r2, r3, addr)                                             \
    asm volatile("ldmatrix.sync.aligned.m8n8.x4.shared.b16 {%0,%1,%2,%3}, [%4];"  \
                 : "=r"(r0), "=r"(r1), "=r"(r2), "=r"(r3) : "r"(addr))

DEVINL void mma16816(float* d, const uint32_t* a, const uint32_t* b) {
    asm volatile(
        "mma.sync.aligned.m16n8k16.row.col.f32.f16.f16.f32 "
        "{%0,%1,%2,%3}, {%4,%5,%6,%7}, {%8,%9}, {%0,%1,%2,%3};"
        : "+f"(d[0]), "+f"(d[1]), "+f"(d[2]), "+f"(d[3])
        : "r"(a[0]), "r"(a[1]), "r"(a[2]), "r"(a[3]), "r"(b[0]), "r"(b[1]));
}

// ---------------- prep (fused w + x): fp32 -> fp16 + inverse row L2 norm -------
__global__ void prep_kernel(const float* __restrict__ x, const float* __restrict__ w) {
    int grow = (blockIdx.x * blockDim.x + threadIdx.x) >> 5;
    int lane = threadIdx.x & 31;

    const float* src;
    __half* dsth;
    float* dstn;
    int row, valid;
    if (grow < C_PAD) {
        src = w; dsth = g_wh; dstn = g_sw; row = grow; valid = C_COLS;
    } else {
        src = x; dsth = g_xh; dstn = g_rx; row = grow - C_PAD; valid = B_ROWS;
        if (row >= B_ROWS) return;
    }

    uint2* drow = reinterpret_cast<uint2*>(dsth + (size_t)row * DIM);
    if (row < valid) {
        const float4* p = reinterpret_cast<const float4*>(src + (size_t)row * DIM);
        float4 v0 = p[lane];
        float4 v1 = p[lane + 32];
        float s = v0.x * v0.x + v0.y * v0.y + v0.z * v0.z + v0.w * v0.w
                + v1.x * v1.x + v1.y * v1.y + v1.z * v1.z + v1.w * v1.w;
#pragma unroll
        for (int o = 16; o; o >>= 1) s += __shfl_xor_sync(0xFFFFFFFFu, s, o);
        __half2 h0 = __floats2half2_rn(v0.x, v0.y);
        __half2 h1 = __floats2half2_rn(v0.z, v0.w);
        __half2 h2 = __floats2half2_rn(v1.x, v1.y);
        __half2 h3 = __floats2half2_rn(v1.z, v1.w);
        uint2 u0, u1;
        u0.x = *reinterpret_cast<uint32_t*>(&h0);
        u0.y = *reinterpret_cast<uint32_t*>(&h1);
        u1.x = *reinterpret_cast<uint32_t*>(&h2);
        u1.y = *reinterpret_cast<uint32_t*>(&h3);
        drow[lane]      = u0;
        drow[lane + 32] = u1;
        if (lane == 0) dstn[row] = rsqrtf(s);
    } else {
        uint2 z = {0u, 0u};
        drow[lane]      = z;
        drow[lane + 32] = z;
        if (lane == 0) dstn[row] = 0.0f;
    }
}

// ---------------- GEMM ----------------
DEVINL void load_b_chunk(uint32_t sB, int n0, int k0, int tid) {
    const __half* wb = g_wh + (size_t)n0 * DIM + k0;
#pragma unroll
    for (int i = 0; i < 4; i++) {                 // 128 rows x 8 x 16B
        int g = tid + i * 256;
        int row = g >> 3, c = g & 7;
        cp16(sB + sw128((uint32_t)(row * 128 + c * 16)), wb + row * DIM + c * 8);
    }
}

__global__ __launch_bounds__(256, 2)
void gemm_kernel(float* __restrict__ out) {
    extern __shared__ char smem[];
    uint32_t s0 = smem_u32(smem);
    uint32_t sA_base = s0 + SM_A;
    uint32_t sB_base = s0 + SM_B;
    uint32_t sRX     = s0 + SM_RX;

    int tid  = threadIdx.x;
    int wid  = tid >> 5;
    int lane = tid & 31;
    int bid  = blockIdx.x;
    int m0      = (bid >> 1) * TILE_M;
    int n0_base = (bid & 1) * (N_TILES * TILE_N);

    // prologue: B0 | A(+rx) | B1  as three cp.async groups
    load_b_chunk(sB_base + 0 * B_STAGE, n0_base, 0 * K_CHUNK, tid);
    cp_commit();
    {
        // A: all 4 chunks, 16 cp16 per thread
        const __half* xa = g_xh + (size_t)m0 * DIM;
#pragma unroll
        for (int kc = 0; kc < K_CHUNKS; kc++) {
#pragma unroll
            for (int i = 0; i < 4; i++) {
                int g = tid + i * 256;
                int row = g >> 3, c = g & 7;
                cp16(sA_base + kc * 16384 + sw128((uint32_t)(row * 128 + c * 16)),
                     xa + row * DIM + kc * K_CHUNK + c * 8);
            }
        }
        if (tid < 32) cp16(sRX + tid * 16, g_rx + m0 + tid * 4);  // 128 floats
        cp_commit();
    }
    load_b_chunk(sB_base + 1 * B_STAGE, n0_base, 1 * K_CHUNK, tid);
    cp_commit();

    int warp_m = wid >> 2;       // 0..1  -> 64 rows
    int warp_n = wid & 3;        // 0..3  -> 32 cols
    int a_row  = warp_m * 64 + (lane & 15);
    int a_kadd = (lane & 16) >> 1;               // 0 or 8
    int b_row  = warp_n * 32 + (lane & 7) + ((lane & 16) >> 1);
    int b_kadd = lane & 8;                       // 0 or 8

    float acc[4][4][4];

#pragma unroll 1
    for (int g = 0; g < N_ITERS; g++) {
        int nt = g >> 2;
        int kc = g & 3;
        if (g < N_ITERS - 1) cp_wait<1>();
        else                 cp_wait<0>();
        __syncthreads();

        // prefetch chunk g+2 into ring slot (g+2)%3 (freed by the sync above)
        if (g + 2 < N_ITERS) {
            int g2 = g + 2;
            load_b_chunk(sB_base + (g2 % N_STAGES) * B_STAGE,
                         n0_base + (g2 >> 2) * TILE_N, (g2 & 3) * K_CHUNK, tid);
            cp_commit();
        }

        if (kc == 0) {
#pragma unroll
            for (int i = 0; i < 4; i++)
#pragma unroll
                for (int j = 0; j < 4; j++)
#pragma unroll
                    for (int k = 0; k < 4; k++) acc[i][j][k] = 0.0f;
        }

        uint32_t sA = sA_base + kc * 16384;
        uint32_t sB = sB_base + (g % N_STAGES) * B_STAGE;
#pragma unroll
        for (int ks = 0; ks < 4; ks++) {
            uint32_t a[4][4];
#pragma unroll
            for (int bm = 0; bm < 4; bm++) {
                int row  = a_row + bm * 16;
                int kcol = ks * 16 + a_kadd;
                LDSM_X4(a[bm][0], a[bm][1], a[bm][2], a[bm][3],
                        sA + sw128((uint32_t)(row * 128 + kcol * 2)));
            }
            uint32_t b[2][4];
#pragma unroll
            for (int bb = 0; bb < 2; bb++) {
                int row  = b_row + bb * 16;
                int kcol = ks * 16 + b_kadd;
                LDSM_X4(b[bb][0], b[bb][1], b[bb][2], b[bb][3],
                        sB + sw128((uint32_t)(row * 128 + kcol * 2)));
            }
#pragma unroll
            for (int bm = 0; bm < 4; bm++)
#pragma unroll
                for (int bb = 0; bb < 2; bb++) {
                    mma16816(acc[bm][2 * bb],     a[bm], &b[bb][0]);
                    mma16816(acc[bm][2 * bb + 1], a[bm], &b[bb][2]);
                }
        }

        // per-n-tile epilogue after its last k-chunk (B loads stay in flight)
        if (kc == 3) {
            int n0 = n0_base + nt * TILE_N;
#pragma unroll
            for (int bm = 0; bm < 4; bm++) {
                int ml = warp_m * 64 + bm * 16 + (lane >> 2);
                float ra = 2.0f * lds_f32(sRX + ml * 4);
                float rb = 2.0f * lds_f32(sRX + (ml + 8) * 4);
                float* rowa = out + (size_t)(m0 + ml) * C_COLS;
                float* rowb = out + (size_t)(m0 + ml + 8) * C_COLS;
#pragma unroll
                for (int bn = 0; bn < 4; bn++) {
                    int col = n0 + warp_n * 32 + bn * 8 + (lane & 3) * 2;
                    if (col < C_COLS) {
                        float sc0 = g_sw[col];
                        float sc1 = g_sw[col + 1];
                        float2 va, vb;
                        va.x = fminf(fmaf(ra * sc0, acc[bm][bn][0], -2.0f), 0.0f);
                        va.y = fminf(fmaf(ra * sc1, acc[bm][bn][1], -2.0f), 0.0f);
                        vb.x = fminf(fmaf(rb * sc0, acc[bm][bn][2], -2.0f), 0.0f);
                        vb.y = fminf(fmaf(rb * sc1, acc[bm][bn][3], -2.0f), 0.0f);
                        *reinterpret_cast<float2*>(rowa + col) = va;
                        *reinterpret_cast<float2*>(rowb + col) = vb;
                    }
                }
            }
        }
    }
}

// ---------------- launch ----------------
extern "C" void kernel_launch(void* const* d_in, const int* in_sizes, int n_in,
                              void* d_out, int out_size) {
    const float* x = (const float*)d_in[0];
    const float* w = (const float*)d_in[1];
    float* out = (float*)d_out;

    cudaFuncSetAttribute(gemm_kernel, cudaFuncAttributeMaxDynamicSharedMemorySize, SMEM_REQ);

    // fused prep: first C_PAD rows -> w, rest -> x
    prep_kernel<<<(C_PAD + B_ROWS) / 8, 256>>>(x, w);

    // 1024 m-tiles x 2 n-halves; each CTA covers 128 x 512
    gemm_kernel<<<(B_ROWS / TILE_M) * 2, 256, SMEM_REQ>>>(out);

    // weight passthrough (second output)
    long long logits_elems = (long long)B_ROWS * C_COLS;
    if ((long long)out_size >= logits_elems + (long long)C_COLS * DIM) {
        cudaMemcpyAsync(out + logits_elems, w, (size_t)C_COLS * DIM * sizeof(float),
                        cudaMemcpyDeviceToDevice);
    }
}

// round 13
// speedup vs baseline: 1.2294x; 1.0799x over previous
#include <cuda_runtime.h>
#include <cuda_fp16.h>
#include <cstdint>

#define DEVINL __device__ __forceinline__

static constexpr int B_ROWS = 131072;
static constexpr int DIM    = 256;
static constexpr int C_COLS = 1000;
static constexpr int C_PAD  = 1024;

// GEMM tiling: CTA 128x128, 8 warps as 2(M) x 4(N) -> warp tile 64x32
static constexpr int TILE_M  = 128;
static constexpr int TILE_N  = 128;
static constexpr int K_CHUNK = 64;                     // fp16 -> 128B smem rows
static constexpr int N_CHUNKS = DIM / K_CHUNK;         // 4
static constexpr int N_STAGES = 3;
static constexpr int STAGE_A = TILE_M * K_CHUNK * 2;   // 16384
static constexpr int STAGE_B = TILE_N * K_CHUNK * 2;   // 16384
static constexpr int STAGE_BYTES = STAGE_A + STAGE_B;  // 32768
static constexpr int SMEM_REQ = N_STAGES * STAGE_BYTES; // 98304 -> 2 CTAs/SM

// scratch
__device__ __half g_xh[(size_t)B_ROWS * DIM];
__device__ __half g_wh[(size_t)C_PAD * DIM];
__device__ float  g_rx[B_ROWS];
__device__ float  g_sw[C_PAD];

// ---------------- helpers ----------------
DEVINL uint32_t smem_u32(const void* p) {
    uint32_t a;
    asm("{ .reg .u64 t; cvta.to.shared.u64 t, %1; cvt.u32.u64 %0, t; }" : "=r"(a) : "l"(p));
    return a;
}
DEVINL void cp16(uint32_t dst, const void* src) {
    asm volatile("cp.async.cg.shared.global [%0], [%1], 16;" :: "r"(dst), "l"(src));
}
DEVINL void cp_commit() { asm volatile("cp.async.commit_group;" ::: "memory"); }
template <int N> DEVINL void cp_wait() {
    asm volatile("cp.async.wait_group %0;" :: "n"(N) : "memory");
}
DEVINL uint32_t sw128(uint32_t off) { return off ^ ((off >> 3) & 0x70); }

#define LDSM_X4(r0, r1, r2, r3, addr)                                             \
    asm volatile("ldmatrix.sync.aligned.m8n8.x4.shared.b16 {%0,%1,%2,%3}, [%4];"  \
                 : "=r"(r0), "=r"(r1), "=r"(r2), "=r"(r3) : "r"(addr))

DEVINL void mma16816(float* d, const uint32_t* a, const uint32_t* b) {
    asm volatile(
        "mma.sync.aligned.m16n8k16.row.col.f32.f16.f16.f32 "
        "{%0,%1,%2,%3}, {%4,%5,%6,%7}, {%8,%9}, {%0,%1,%2,%3};"
        : "+f"(d[0]), "+f"(d[1]), "+f"(d[2]), "+f"(d[3])
        : "r"(a[0]), "r"(a[1]), "r"(a[2]), "r"(a[3]), "r"(b[0]), "r"(b[1]));
}

// ---------------- prep: 2 rows/warp, fp32->fp16 + rsqrt norm + w passthrough ---
DEVINL void prep_row_store(__half* dsth, float* dstn, int row, int lane,
                           const float4& v0, const float4& v1, bool ok) {
    uint2* drow = reinterpret_cast<uint2*>(dsth + (size_t)row * DIM);
    if (ok) {
        float s = v0.x * v0.x + v0.y * v0.y + v0.z * v0.z + v0.w * v0.w
                + v1.x * v1.x + v1.y * v1.y + v1.z * v1.z + v1.w * v1.w;
#pragma unroll
        for (int o = 16; o; o >>= 1) s += __shfl_xor_sync(0xFFFFFFFFu, s, o);
        __half2 h0 = __floats2half2_rn(v0.x, v0.y);
        __half2 h1 = __floats2half2_rn(v0.z, v0.w);
        __half2 h2 = __floats2half2_rn(v1.x, v1.y);
        __half2 h3 = __floats2half2_rn(v1.z, v1.w);
        uint2 u0, u1;
        u0.x = *reinterpret_cast<uint32_t*>(&h0);
        u0.y = *reinterpret_cast<uint32_t*>(&h1);
        u1.x = *reinterpret_cast<uint32_t*>(&h2);
        u1.y = *reinterpret_cast<uint32_t*>(&h3);
        drow[lane]      = u0;
        drow[lane + 32] = u1;
        if (lane == 0) dstn[row] = rsqrtf(s);
    } else {
        uint2 z = {0u, 0u};
        drow[lane]      = z;
        drow[lane + 32] = z;
        if (lane == 0) dstn[row] = 0.0f;
    }
}

__global__ void prep_kernel(const float* __restrict__ x, const float* __restrict__ w,
                            float* __restrict__ wout) {
    int wp   = (blockIdx.x * blockDim.x + threadIdx.x) >> 5;
    int lane = threadIdx.x & 31;

    const float* src;
    __half* dsth;
    float* dstn;
    int row0, valid;
    bool isw;
    if (wp < C_PAD / 2) {
        src = w; dsth = g_wh; dstn = g_sw; row0 = wp * 2; valid = C_COLS; isw = true;
    } else {
        src = x; dsth = g_xh; dstn = g_rx; row0 = (wp - C_PAD / 2) * 2;
        valid = B_ROWS; isw = false;
        if (row0 >= B_ROWS) return;
    }
    bool ok0 = row0 < valid;
    bool ok1 = row0 + 1 < valid;

    // 4 independent LDG.128 in flight (MLP=4)
    float4 a0 = {}, a1 = {}, b0 = {}, b1 = {};
    const float4* p0 = reinterpret_cast<const float4*>(src + (size_t)row0 * DIM);
    const float4* p1 = reinterpret_cast<const float4*>(src + (size_t)(row0 + 1) * DIM);
    if (ok0) { a0 = p0[lane]; a1 = p0[lane + 32]; }
    if (ok1) { b0 = p1[lane]; b1 = p1[lane + 32]; }

    prep_row_store(dsth, dstn, row0,     lane, a0, a1, ok0);
    prep_row_store(dsth, dstn, row0 + 1, lane, b0, b1, ok1);

    // w passthrough (second output): copy the fp32 rows we already hold
    if (isw && wout != nullptr) {
        if (ok0) {
            float4* o = reinterpret_cast<float4*>(wout + (size_t)row0 * DIM);
            o[lane] = a0; o[lane + 32] = a1;
        }
        if (ok1) {
            float4* o = reinterpret_cast<float4*>(wout + (size_t)(row0 + 1) * DIM);
            o[lane] = b0; o[lane + 32] = b1;
        }
    }
}

// ---------------- GEMM (unchanged from the 236.8us / 204us-gemm version) ------
DEVINL void load_chunk(uint32_t sA, uint32_t sB, int m0, int n0, int k0, int tid) {
    const __half* xa = g_xh + (size_t)m0 * DIM + k0;
    const __half* wb = g_wh + (size_t)n0 * DIM + k0;
#pragma unroll
    for (int i = 0; i < 4; i++) {                 // A: 128 rows x 8 x 16B
        int g = tid + i * 256;
        int row = g >> 3, c = g & 7;
        cp16(sA + sw128((uint32_t)(row * 128 + c * 16)), xa + row * DIM + c * 8);
    }
#pragma unroll
    for (int i = 0; i < 4; i++) {                 // B: 128 rows x 8 x 16B
        int g = tid + i * 256;
        int row = g >> 3, c = g & 7;
        cp16(sB + sw128((uint32_t)(row * 128 + c * 16)), wb + row * DIM + c * 8);
    }
}

__global__ __launch_bounds__(256, 2)
void gemm_kernel(float* __restrict__ out) {
    extern __shared__ char smem[];
    uint32_t s0 = smem_u32(smem);

    int tid  = threadIdx.x;
    int wid  = tid >> 5;
    int lane = tid & 31;
    int bid  = blockIdx.x;
    int m0 = (bid >> 3) * TILE_M;
    int n0 = (bid & 7) * TILE_N;

    // prologue: prefetch chunks 0,1 into buffers 0,1
    load_chunk(s0, s0 + STAGE_A, m0, n0, 0 * K_CHUNK, tid);
    cp_commit();
    load_chunk(s0 + STAGE_BYTES, s0 + STAGE_BYTES + STAGE_A, m0, n0, 1 * K_CHUNK, tid);
    cp_commit();

    float acc[4][4][4];
#pragma unroll
    for (int i = 0; i < 4; i++)
#pragma unroll
        for (int j = 0; j < 4; j++)
#pragma unroll
            for (int k = 0; k < 4; k++) acc[i][j][k] = 0.0f;

    int warp_m = wid >> 2;       // 0..1  -> 64 rows
    int warp_n = wid & 3;        // 0..3  -> 32 cols

    int a_row  = warp_m * 64 + (lane & 15);
    int a_kadd = (lane & 16) >> 1;               // 0 or 8
    int b_row  = warp_n * 32 + (lane & 7) + ((lane & 16) >> 1);
    int b_kadd = lane & 8;                       // 0 or 8

#pragma unroll
    for (int c = 0; c < N_CHUNKS; c++) {
        if (c < N_CHUNKS - 1) cp_wait<1>();
        else                  cp_wait<0>();
        __syncthreads();

        // prefetch chunk c+2 into buffer (c+2)%3 == (c-1)%3, freed by the sync above
        if (c + 2 < N_CHUNKS) {
            uint32_t sp = s0 + ((c + 2) % N_STAGES) * STAGE_BYTES;
            load_chunk(sp, sp + STAGE_A, m0, n0, (c + 2) * K_CHUNK, tid);
            cp_commit();
        }

        uint32_t sA = s0 + (c % N_STAGES) * STAGE_BYTES;
        uint32_t sB = sA + STAGE_A;
#pragma unroll
        for (int ks = 0; ks < 4; ks++) {
            uint32_t a[4][4];
#pragma unroll
            for (int bm = 0; bm < 4; bm++) {
                int row  = a_row + bm * 16;
                int kcol = ks * 16 + a_kadd;
                LDSM_X4(a[bm][0], a[bm][1], a[bm][2], a[bm][3],
                        sA + sw128((uint32_t)(row * 128 + kcol * 2)));
            }
            uint32_t b[2][4];
#pragma unroll
            for (int bb = 0; bb < 2; bb++) {
                int row  = b_row + bb * 16;
                int kcol = ks * 16 + b_kadd;
                LDSM_X4(b[bb][0], b[bb][1], b[bb][2], b[bb][3],
                        sB + sw128((uint32_t)(row * 128 + kcol * 2)));
            }
#pragma unroll
            for (int bm = 0; bm < 4; bm++)
#pragma unroll
                for (int bb = 0; bb < 2; bb++) {
                    mma16816(acc[bm][2 * bb],     a[bm], &b[bb][0]);
                    mma16816(acc[bm][2 * bb + 1], a[bm], &b[bb][2]);
                }
        }
    }

    // ---------------- epilogue ----------------
#pragma unroll
    for (int bm = 0; bm < 4; bm++) {
        int ma = m0 + warp_m * 64 + bm * 16 + (lane >> 2);
        int mb = ma + 8;
        float ra = 2.0f * g_rx[ma];
        float rb = 2.0f * g_rx[mb];
        float* rowa = out + (size_t)ma * C_COLS;
        float* rowb = out + (size_t)mb * C_COLS;
#pragma unroll
        for (int bn = 0; bn < 4; bn++) {
            int col = n0 + warp_n * 32 + bn * 8 + (lane & 3) * 2;
            if (col < C_COLS) {
                float sc0 = g_sw[col];
                float sc1 = g_sw[col + 1];
                float2 va, vb;
                va.x = fminf(fmaf(ra * sc0, acc[bm][bn][0], -2.0f), 0.0f);
                va.y = fminf(fmaf(ra * sc1, acc[bm][bn][1], -2.0f), 0.0f);
                vb.x = fminf(fmaf(rb * sc0, acc[bm][bn][2], -2.0f), 0.0f);
                vb.y = fminf(fmaf(rb * sc1, acc[bm][bn][3], -2.0f), 0.0f);
                *reinterpret_cast<float2*>(rowa + col) = va;
                *reinterpret_cast<float2*>(rowb + col) = vb;
            }
        }
    }
}

// ---------------- launch ----------------
extern "C" void kernel_launch(void* const* d_in, const int* in_sizes, int n_in,
                              void* d_out, int out_size) {
    const float* x = (const float*)d_in[0];
    const float* w = (const float*)d_in[1];
    float* out = (float*)d_out;

    cudaFuncSetAttribute(gemm_kernel, cudaFuncAttributeMaxDynamicSharedMemorySize, SMEM_REQ);

    // passthrough destination (if out has room for the second output)
    long long logits_elems = (long long)B_ROWS * C_COLS;
    float* wout = nullptr;
    if ((long long)out_size >= logits_elems + (long long)C_COLS * DIM)
        wout = out + logits_elems;

    // fused prep: 2 rows per warp; first C_PAD/2 warps -> w (+passthrough), rest -> x
    {
        int total_warps = C_PAD / 2 + B_ROWS / 2;      // 66048
        int blocks = (total_warps * 32 + 255) / 256;   // 8256
        prep_kernel<<<blocks, 256>>>(x, w, wout);
    }

    // GEMM: 1024 m-tiles x 8 n-tiles; n fastest for x L2 reuse
    gemm_kernel<<<(B_ROWS / TILE_M) * 8, 256, SMEM_REQ>>>(out);
}

// round 14
// speedup vs baseline: 1.2599x; 1.0248x over previous
#include <cuda_runtime.h>
#include <cuda_fp16.h>
#include <cstdint>

#define DEVINL __device__ __forceinline__

static constexpr int B_ROWS = 131072;
static constexpr int DIM    = 256;
static constexpr int C_COLS = 1000;
static constexpr int C_PAD  = 1024;

// CTA 128x256, 8 warps as 2(M) x 4(N) -> warp tile 64x64, f16 accumulate
static constexpr int TILE_M   = 128;
static constexpr int TILE_N   = 256;
static constexpr int K_CHUNK  = 32;                    // 64B smem rows (SW64)
static constexpr int N_CHUNKS = DIM / K_CHUNK;         // 8
static constexpr int N_STAGES = 4;
static constexpr int STAGE_A  = TILE_M * K_CHUNK * 2;  // 8192
static constexpr int STAGE_B  = TILE_N * K_CHUNK * 2;  // 16384
static constexpr int STAGE_BYTES = STAGE_A + STAGE_B;  // 24576
static constexpr int SMEM_REQ = N_STAGES * STAGE_BYTES; // 98304 -> 2 CTAs/SM

// scratch: PRE-NORMALIZED fp16 rows (unit L2 norm); zero rows for w padding
__device__ __half g_xn[(size_t)B_ROWS * DIM];
__device__ __half g_wn[(size_t)C_PAD * DIM];

// ---------------- helpers ----------------
DEVINL uint32_t smem_u32(const void* p) {
    uint32_t a;
    asm("{ .reg .u64 t; cvta.to.shared.u64 t, %1; cvt.u32.u64 %0, t; }" : "=r"(a) : "l"(p));
    return a;
}
DEVINL void cp16(uint32_t dst, const void* src) {
    asm volatile("cp.async.cg.shared.global [%0], [%1], 16;" :: "r"(dst), "l"(src));
}
DEVINL void cp_commit() { asm volatile("cp.async.commit_group;" ::: "memory"); }
template <int N> DEVINL void cp_wait() {
    asm volatile("cp.async.wait_group %0;" :: "n"(N) : "memory");
}
DEVINL uint32_t sw64(uint32_t off) { return off ^ ((off >> 3) & 0x30); }

#define LDSM_X4(r0, r1, r2, r3, addr)                                             \
    asm volatile("ldmatrix.sync.aligned.m8n8.x4.shared.b16 {%0,%1,%2,%3}, [%4];"  \
                 : "=r"(r0), "=r"(r1), "=r"(r2), "=r"(r3) : "r"(addr))

DEVINL void mma16816_f16(uint32_t* d, const uint32_t* a, const uint32_t* b) {
    asm volatile(
        "mma.sync.aligned.m16n8k16.row.col.f16.f16.f16.f16 "
        "{%0,%1}, {%2,%3,%4,%5}, {%6,%7}, {%0,%1};"
        : "+r"(d[0]), "+r"(d[1])
        : "r"(a[0]), "r"(a[1]), "r"(a[2]), "r"(a[3]), "r"(b[0]), "r"(b[1]));
}

// ---------------- prep: 2 rows/warp, fp32 -> NORMALIZED fp16 + w passthrough ---
DEVINL void prep_row_store(__half* dsth, int row, int lane,
                           const float4& v0, const float4& v1, bool ok) {
    uint2* drow = reinterpret_cast<uint2*>(dsth + (size_t)row * DIM);
    if (ok) {
        float s = v0.x * v0.x + v0.y * v0.y + v0.z * v0.z + v0.w * v0.w
                + v1.x * v1.x + v1.y * v1.y + v1.z * v1.z + v1.w * v1.w;
#pragma unroll
        for (int o = 16; o; o >>= 1) s += __shfl_xor_sync(0xFFFFFFFFu, s, o);
        float rn = rsqrtf(fmaxf(s, 1e-24f));
        __half2 h0 = __floats2half2_rn(v0.x * rn, v0.y * rn);
        __half2 h1 = __floats2half2_rn(v0.z * rn, v0.w * rn);
        __half2 h2 = __floats2half2_rn(v1.x * rn, v1.y * rn);
        __half2 h3 = __floats2half2_rn(v1.z * rn, v1.w * rn);
        uint2 u0, u1;
        u0.x = *reinterpret_cast<uint32_t*>(&h0);
        u0.y = *reinterpret_cast<uint32_t*>(&h1);
        u1.x = *reinterpret_cast<uint32_t*>(&h2);
        u1.y = *reinterpret_cast<uint32_t*>(&h3);
        drow[lane]      = u0;
        drow[lane + 32] = u1;
    } else {
        uint2 z = {0u, 0u};
        drow[lane]      = z;
        drow[lane + 32] = z;
    }
}

__global__ void prep_kernel(const float* __restrict__ x, const float* __restrict__ w,
                            float* __restrict__ wout) {
    int wp   = (blockIdx.x * blockDim.x + threadIdx.x) >> 5;
    int lane = threadIdx.x & 31;

    const float* src;
    __half* dsth;
    int row0, valid;
    bool isw;
    if (wp < C_PAD / 2) {
        src = w; dsth = g_wn; row0 = wp * 2; valid = C_COLS; isw = true;
    } else {
        src = x; dsth = g_xn; row0 = (wp - C_PAD / 2) * 2;
        valid = B_ROWS; isw = false;
        if (row0 >= B_ROWS) return;
    }
    bool ok0 = row0 < valid;
    bool ok1 = row0 + 1 < valid;

    float4 a0 = {}, a1 = {}, b0 = {}, b1 = {};
    const float4* p0 = reinterpret_cast<const float4*>(src + (size_t)row0 * DIM);
    const float4* p1 = reinterpret_cast<const float4*>(src + (size_t)(row0 + 1) * DIM);
    if (ok0) { a0 = p0[lane]; a1 = p0[lane + 32]; }
    if (ok1) { b0 = p1[lane]; b1 = p1[lane + 32]; }

    prep_row_store(dsth, row0,     lane, a0, a1, ok0);
    prep_row_store(dsth, row0 + 1, lane, b0, b1, ok1);

    if (isw && wout != nullptr) {
        if (ok0) {
            float4* o = reinterpret_cast<float4*>(wout + (size_t)row0 * DIM);
            o[lane] = a0; o[lane + 32] = a1;
        }
        if (ok1) {
            float4* o = reinterpret_cast<float4*>(wout + (size_t)(row0 + 1) * DIM);
            o[lane] = b0; o[lane + 32] = b1;
        }
    }
}

// ---------------- GEMM ----------------
DEVINL void load_chunk(uint32_t stage, int m0, int n0, int k0, int tid) {
    const __half* xa = g_xn + (size_t)m0 * DIM + k0;
    const __half* wb = g_wn + (size_t)n0 * DIM + k0;
    uint32_t sA = stage;
    uint32_t sB = stage + STAGE_A;
    // A: 128 rows x 4 x 16B (512 units)
#pragma unroll
    for (int i = 0; i < 2; i++) {
        int g = tid + i * 256;
        int row = g >> 2, c = g & 3;
        cp16(sA + sw64((uint32_t)(row * 64 + c * 16)), xa + row * DIM + c * 8);
    }
    // B: 256 rows x 4 x 16B (1024 units)
#pragma unroll
    for (int i = 0; i < 4; i++) {
        int g = tid + i * 256;
        int row = g >> 2, c = g & 3;
        cp16(sB + sw64((uint32_t)(row * 64 + c * 16)), wb + row * DIM + c * 8);
    }
}

__global__ __launch_bounds__(256, 2)
void gemm_kernel(float* __restrict__ out) {
    extern __shared__ char smem[];
    uint32_t s0 = smem_u32(smem);

    int tid  = threadIdx.x;
    int wid  = tid >> 5;
    int lane = tid & 31;
    int bid  = blockIdx.x;
    int m0 = (bid >> 2) * TILE_M;
    int n0 = (bid & 3) * TILE_N;

    // prologue: chunks 0..2
    load_chunk(s0 + 0 * STAGE_BYTES, m0, n0, 0 * K_CHUNK, tid); cp_commit();
    load_chunk(s0 + 1 * STAGE_BYTES, m0, n0, 1 * K_CHUNK, tid); cp_commit();
    load_chunk(s0 + 2 * STAGE_BYTES, m0, n0, 2 * K_CHUNK, tid); cp_commit();

    uint32_t acc[4][8][2];
#pragma unroll
    for (int i = 0; i < 4; i++)
#pragma unroll
        for (int j = 0; j < 8; j++) { acc[i][j][0] = 0u; acc[i][j][1] = 0u; }

    int warp_m = wid >> 2;       // 0..1  -> 64 rows
    int warp_n = wid & 3;        // 0..3  -> 64 cols

    int a_row = warp_m * 64 + (lane & 15);
    int a_kb  = lane & 16;                         // 0 or 16 bytes
    int b_rwo = warp_n * 64 + (lane & 7) + ((lane & 16) >> 1);
    int b_kb  = (lane & 8) << 1;                   // 0 or 16 bytes

#pragma unroll 1
    for (int c = 0; c < N_CHUNKS; c++) {
        if      (c <= N_CHUNKS - 3) cp_wait<2>();
        else if (c == N_CHUNKS - 2) cp_wait<1>();
        else                        cp_wait<0>();
        __syncthreads();

        // prefetch chunk c+3 into ring slot (c+3)%4 == (c-1)%4 (freed by sync)
        if (c + 3 < N_CHUNKS) {
            load_chunk(s0 + ((c + 3) % N_STAGES) * STAGE_BYTES,
                       m0, n0, (c + 3) * K_CHUNK, tid);
            cp_commit();
        }

        uint32_t sA = s0 + (c % N_STAGES) * STAGE_BYTES;
        uint32_t sB = sA + STAGE_A;
#pragma unroll
        for (int ks = 0; ks < 2; ks++) {
            uint32_t a[4][4];
#pragma unroll
            for (int bm = 0; bm < 4; bm++) {
                int row = a_row + bm * 16;
                LDSM_X4(a[bm][0], a[bm][1], a[bm][2], a[bm][3],
                        sA + sw64((uint32_t)(row * 64 + ks * 32 + a_kb)));
            }
            uint32_t b[4][4];
#pragma unroll
            for (int bb = 0; bb < 4; bb++) {
                int row = b_rwo + bb * 16;
                LDSM_X4(b[bb][0], b[bb][1], b[bb][2], b[bb][3],
                        sB + sw64((uint32_t)(row * 64 + ks * 32 + b_kb)));
            }
#pragma unroll
            for (int bm = 0; bm < 4; bm++)
#pragma unroll
                for (int bb = 0; bb < 4; bb++) {
                    mma16816_f16(acc[bm][2 * bb],     a[bm], &b[bb][0]);
                    mma16816_f16(acc[bm][2 * bb + 1], a[bm], &b[bb][2]);
                }
        }
    }

    // ---------------- epilogue: logits = min(2*dot - 2, 0) ----------------
#pragma unroll
    for (int bm = 0; bm < 4; bm++) {
        int ma = m0 + warp_m * 64 + bm * 16 + (lane >> 2);
        int mb = ma + 8;
        float* rowa = out + (size_t)ma * C_COLS;
        float* rowb = out + (size_t)mb * C_COLS;
#pragma unroll
        for (int bn = 0; bn < 8; bn++) {
            int col = n0 + warp_n * 64 + bn * 8 + (lane & 3) * 2;
            if (col < C_COLS) {
                float2 fa = __half22float2(*reinterpret_cast<__half2*>(&acc[bm][bn][0]));
                float2 fb = __half22float2(*reinterpret_cast<__half2*>(&acc[bm][bn][1]));
                float2 va, vb;
                va.x = fminf(fmaf(2.0f, fa.x, -2.0f), 0.0f);
                va.y = fminf(fmaf(2.0f, fa.y, -2.0f), 0.0f);
                vb.x = fminf(fmaf(2.0f, fb.x, -2.0f), 0.0f);
                vb.y = fminf(fmaf(2.0f, fb.y, -2.0f), 0.0f);
                *reinterpret_cast<float2*>(rowa + col) = va;
                *reinterpret_cast<float2*>(rowb + col) = vb;
            }
        }
    }
}

// ---------------- launch ----------------
extern "C" void kernel_launch(void* const* d_in, const int* in_sizes, int n_in,
                              void* d_out, int out_size) {
    const float* x = (const float*)d_in[0];
    const float* w = (const float*)d_in[1];
    float* out = (float*)d_out;

    cudaFuncSetAttribute(gemm_kernel, cudaFuncAttributeMaxDynamicSharedMemorySize, SMEM_REQ);

    long long logits_elems = (long long)B_ROWS * C_COLS;
    float* wout = nullptr;
    if ((long long)out_size >= logits_elems + (long long)C_COLS * DIM)
        wout = out + logits_elems;

    {
        int total_warps = C_PAD / 2 + B_ROWS / 2;      // 66048
        int blocks = (total_warps * 32 + 255) / 256;   // 8256
        prep_kernel<<<blocks, 256>>>(x, w, wout);
    }

    // 1024 m-tiles x 4 n-tiles (n fastest for x L2 reuse)
    gemm_kernel<<<(B_ROWS / TILE_M) * 4, 256, SMEM_REQ>>>(out);
}

// round 15
// speedup vs baseline: 1.2728x; 1.0103x over previous
#include <cuda_runtime.h>
#include <cuda_fp16.h>
#include <cstdint>

#define DEVINL __device__ __forceinline__

static constexpr int B_ROWS = 131072;
static constexpr int DIM    = 256;
static constexpr int C_COLS = 1000;
static constexpr int C_PAD  = 1024;

// CTA 128x128, 8 warps as 2(M) x 4(N) -> warp tile 64x32, f16 accumulate
static constexpr int TILE_M   = 128;
static constexpr int TILE_N   = 128;
static constexpr int K_CHUNK  = 32;                    // 64B smem rows (SW64)
static constexpr int N_CHUNKS = DIM / K_CHUNK;         // 8
static constexpr int N_STAGES = 4;
static constexpr int STAGE_A  = TILE_M * K_CHUNK * 2;  // 8192
static constexpr int STAGE_B  = TILE_N * K_CHUNK * 2;  // 8192
static constexpr int STAGE_BYTES = STAGE_A + STAGE_B;  // 16384
static constexpr int SMEM_REQ = N_STAGES * STAGE_BYTES; // 65536 -> 3 CTAs/SM

// scratch: PRE-NORMALIZED fp16 rows (unit L2 norm); zero rows for w padding
__device__ __half g_xn[(size_t)B_ROWS * DIM];
__device__ __half g_wn[(size_t)C_PAD * DIM];

// ---------------- helpers ----------------
DEVINL uint32_t smem_u32(const void* p) {
    uint32_t a;
    asm("{ .reg .u64 t; cvta.to.shared.u64 t, %1; cvt.u32.u64 %0, t; }" : "=r"(a) : "l"(p));
    return a;
}
DEVINL void cp16(uint32_t dst, const void* src) {
    asm volatile("cp.async.cg.shared.global [%0], [%1], 16;" :: "r"(dst), "l"(src));
}
DEVINL void cp_commit() { asm volatile("cp.async.commit_group;" ::: "memory"); }
template <int N> DEVINL void cp_wait() {
    asm volatile("cp.async.wait_group %0;" :: "n"(N) : "memory");
}
DEVINL uint32_t sw64(uint32_t off) { return off ^ ((off >> 3) & 0x30); }

#define LDSM_X4(r0, r1, r2, r3, addr)                                             \
    asm volatile("ldmatrix.sync.aligned.m8n8.x4.shared.b16 {%0,%1,%2,%3}, [%4];"  \
                 : "=r"(r0), "=r"(r1), "=r"(r2), "=r"(r3) : "r"(addr))

DEVINL void mma16816_f16(uint32_t* d, const uint32_t* a, const uint32_t* b) {
    asm volatile(
        "mma.sync.aligned.m16n8k16.row.col.f16.f16.f16.f16 "
        "{%0,%1}, {%2,%3,%4,%5}, {%6,%7}, {%0,%1};"
        : "+r"(d[0]), "+r"(d[1])
        : "r"(a[0]), "r"(a[1]), "r"(a[2]), "r"(a[3]), "r"(b[0]), "r"(b[1]));
}

// ---------------- prep: 2 rows/warp, fp32 -> NORMALIZED fp16 + w passthrough ---
DEVINL void prep_row_store(__half* dsth, int row, int lane,
                           const float4& v0, const float4& v1, bool ok) {
    uint2* drow = reinterpret_cast<uint2*>(dsth + (size_t)row * DIM);
    if (ok) {
        float s = v0.x * v0.x + v0.y * v0.y + v0.z * v0.z + v0.w * v0.w
                + v1.x * v1.x + v1.y * v1.y + v1.z * v1.z + v1.w * v1.w;
#pragma unroll
        for (int o = 16; o; o >>= 1) s += __shfl_xor_sync(0xFFFFFFFFu, s, o);
        float rn = rsqrtf(fmaxf(s, 1e-24f));
        __half2 h0 = __floats2half2_rn(v0.x * rn, v0.y * rn);
        __half2 h1 = __floats2half2_rn(v0.z * rn, v0.w * rn);
        __half2 h2 = __floats2half2_rn(v1.x * rn, v1.y * rn);
        __half2 h3 = __floats2half2_rn(v1.z * rn, v1.w * rn);
        uint2 u0, u1;
        u0.x = *reinterpret_cast<uint32_t*>(&h0);
        u0.y = *reinterpret_cast<uint32_t*>(&h1);
        u1.x = *reinterpret_cast<uint32_t*>(&h2);
        u1.y = *reinterpret_cast<uint32_t*>(&h3);
        drow[lane]      = u0;
        drow[lane + 32] = u1;
    } else {
        uint2 z = {0u, 0u};
        drow[lane]      = z;
        drow[lane + 32] = z;
    }
}

__global__ void prep_kernel(const float* __restrict__ x, const float* __restrict__ w,
                            float* __restrict__ wout) {
    int wp   = (blockIdx.x * blockDim.x + threadIdx.x) >> 5;
    int lane = threadIdx.x & 31;

    const float* src;
    __half* dsth;
    int row0, valid;
    bool isw;
    if (wp < C_PAD / 2) {
        src = w; dsth = g_wn; row0 = wp * 2; valid = C_COLS; isw = true;
    } else {
        src = x; dsth = g_xn; row0 = (wp - C_PAD / 2) * 2;
        valid = B_ROWS; isw = false;
        if (row0 >= B_ROWS) return;
    }
    bool ok0 = row0 < valid;
    bool ok1 = row0 + 1 < valid;

    float4 a0 = {}, a1 = {}, b0 = {}, b1 = {};
    const float4* p0 = reinterpret_cast<const float4*>(src + (size_t)row0 * DIM);
    const float4* p1 = reinterpret_cast<const float4*>(src + (size_t)(row0 + 1) * DIM);
    if (ok0) { a0 = p0[lane]; a1 = p0[lane + 32]; }
    if (ok1) { b0 = p1[lane]; b1 = p1[lane + 32]; }

    prep_row_store(dsth, row0,     lane, a0, a1, ok0);
    prep_row_store(dsth, row0 + 1, lane, b0, b1, ok1);

    if (isw && wout != nullptr) {
        if (ok0) {
            float4* o = reinterpret_cast<float4*>(wout + (size_t)row0 * DIM);
            o[lane] = a0; o[lane + 32] = a1;
        }
        if (ok1) {
            float4* o = reinterpret_cast<float4*>(wout + (size_t)(row0 + 1) * DIM);
            o[lane] = b0; o[lane + 32] = b1;
        }
    }
}

// ---------------- GEMM ----------------
DEVINL void load_chunk(uint32_t stage, int m0, int n0, int k0, int tid) {
    const __half* xa = g_xn + (size_t)m0 * DIM + k0;
    const __half* wb = g_wn + (size_t)n0 * DIM + k0;
    uint32_t sA = stage;
    uint32_t sB = stage + STAGE_A;
    // A: 128 rows x 4 x 16B (512 units), 2 iters of 256 threads
#pragma unroll
    for (int i = 0; i < 2; i++) {
        int g = tid + i * 256;
        int row = g >> 2, c = g & 3;
        cp16(sA + sw64((uint32_t)(row * 64 + c * 16)), xa + row * DIM + c * 8);
    }
    // B: 128 rows x 4 x 16B (512 units)
#pragma unroll
    for (int i = 0; i < 2; i++) {
        int g = tid + i * 256;
        int row = g >> 2, c = g & 3;
        cp16(sB + sw64((uint32_t)(row * 64 + c * 16)), wb + row * DIM + c * 8);
    }
}

__global__ __launch_bounds__(256, 3)
void gemm_kernel(float* __restrict__ out) {
    extern __shared__ char smem[];
    uint32_t s0 = smem_u32(smem);

    int tid  = threadIdx.x;
    int wid  = tid >> 5;
    int lane = tid & 31;
    int bid  = blockIdx.x;
    int m0 = (bid >> 3) * TILE_M;
    int n0 = (bid & 7) * TILE_N;

    // prologue: chunks 0..2
    load_chunk(s0 + 0 * STAGE_BYTES, m0, n0, 0 * K_CHUNK, tid); cp_commit();
    load_chunk(s0 + 1 * STAGE_BYTES, m0, n0, 1 * K_CHUNK, tid); cp_commit();
    load_chunk(s0 + 2 * STAGE_BYTES, m0, n0, 2 * K_CHUNK, tid); cp_commit();

    uint32_t acc[4][4][2];
#pragma unroll
    for (int i = 0; i < 4; i++)
#pragma unroll
        for (int j = 0; j < 4; j++) { acc[i][j][0] = 0u; acc[i][j][1] = 0u; }

    int warp_m = wid >> 2;       // 0..1  -> 64 rows
    int warp_n = wid & 3;        // 0..3  -> 32 cols

    int a_row = warp_m * 64 + (lane & 15);
    int a_kb  = lane & 16;                         // 0 or 16 bytes
    int b_rwo = warp_n * 32 + (lane & 7) + ((lane & 16) >> 1);
    int b_kb  = (lane & 8) << 1;                   // 0 or 16 bytes

#pragma unroll 1
    for (int c = 0; c < N_CHUNKS; c++) {
        if      (c <= N_CHUNKS - 3) cp_wait<2>();
        else if (c == N_CHUNKS - 2) cp_wait<1>();
        else                        cp_wait<0>();
        __syncthreads();

        // prefetch chunk c+3 into ring slot (c+3)%4 == (c-1)%4 (freed by sync)
        if (c + 3 < N_CHUNKS) {
            load_chunk(s0 + ((c + 3) % N_STAGES) * STAGE_BYTES,
                       m0, n0, (c + 3) * K_CHUNK, tid);
            cp_commit();
        }

        uint32_t sA = s0 + (c % N_STAGES) * STAGE_BYTES;
        uint32_t sB = sA + STAGE_A;
#pragma unroll
        for (int ks = 0; ks < 2; ks++) {
            uint32_t a[4][4];
#pragma unroll
            for (int bm = 0; bm < 4; bm++) {
                int row = a_row + bm * 16;
                LDSM_X4(a[bm][0], a[bm][1], a[bm][2], a[bm][3],
                        sA + sw64((uint32_t)(row * 64 + ks * 32 + a_kb)));
            }
            uint32_t b[2][4];
#pragma unroll
            for (int bb = 0; bb < 2; bb++) {
                int row = b_rwo + bb * 16;
                LDSM_X4(b[bb][0], b[bb][1], b[bb][2], b[bb][3],
                        sB + sw64((uint32_t)(row * 64 + ks * 32 + b_kb)));
            }
#pragma unroll
            for (int bm = 0; bm < 4; bm++)
#pragma unroll
                for (int bb = 0; bb < 2; bb++) {
                    mma16816_f16(acc[bm][2 * bb],     a[bm], &b[bb][0]);
                    mma16816_f16(acc[bm][2 * bb + 1], a[bm], &b[bb][2]);
                }
        }
    }

    // ---------------- epilogue: logits = min(2*dot - 2, 0) ----------------
#pragma unroll
    for (int bm = 0; bm < 4; bm++) {
        int ma = m0 + warp_m * 64 + bm * 16 + (lane >> 2);
        int mb = ma + 8;
        float* rowa = out + (size_t)ma * C_COLS;
        float* rowb = out + (size_t)mb * C_COLS;
#pragma unroll
        for (int bn = 0; bn < 4; bn++) {
            int col = n0 + warp_n * 32 + bn * 8 + (lane & 3) * 2;
            if (col < C_COLS) {
                float2 fa = __half22float2(*reinterpret_cast<__half2*>(&acc[bm][bn][0]));
                float2 fb = __half22float2(*reinterpret_cast<__half2*>(&acc[bm][bn][1]));
                float2 va, vb;
                va.x = fminf(fmaf(2.0f, fa.x, -2.0f), 0.0f);
                va.y = fminf(fmaf(2.0f, fa.y, -2.0f), 0.0f);
                vb.x = fminf(fmaf(2.0f, fb.x, -2.0f), 0.0f);
                vb.y = fminf(fmaf(2.0f, fb.y, -2.0f), 0.0f);
                *reinterpret_cast<float2*>(rowa + col) = va;
                *reinterpret_cast<float2*>(rowb + col) = vb;
            }
        }
    }
}

// ---------------- launch ----------------
extern "C" void kernel_launch(void* const* d_in, const int* in_sizes, int n_in,
                              void* d_out, int out_size) {
    const float* x = (const float*)d_in[0];
    const float* w = (const float*)d_in[1];
    float* out = (float*)d_out;

    cudaFuncSetAttribute(gemm_kernel, cudaFuncAttributeMaxDynamicSharedMemorySize, SMEM_REQ);

    long long logits_elems = (long long)B_ROWS * C_COLS;
    float* wout = nullptr;
    if ((long long)out_size >= logits_elems + (long long)C_COLS * DIM)
        wout = out + logits_elems;

    {
        int total_warps = C_PAD / 2 + B_ROWS / 2;      // 66048
        int blocks = (total_warps * 32 + 255) / 256;   // 8256
        prep_kernel<<<blocks, 256>>>(x, w, wout);
    }

    // 1024 m-tiles x 8 n-tiles (n fastest for x L2 reuse)
    gemm_kernel<<<(B_ROWS / TILE_M) * 8, 256, SMEM_REQ>>>(out);
}